// round 7
// baseline (speedup 1.0000x reference)
#include <cuda_runtime.h>
#include <cuda_fp16.h>

#define NSEG   128
#define SDIM   32
#define TDIM   32
#define NWARPS 4
#define NTHREADS 128
#define SPLIT  11
#define NBINS  34                 // bin = r+1, r in [-1, 32]
#define PITCH  32                 // word addr = 32*bin + t  ->  bank = t (conflict-free)

__device__ int g_bounds[NSEG + 1];

__device__ __forceinline__ long long ld_idx(const void* p, int i, bool is64) {
    return is64 ? ((const long long*)p)[i] : (long long)((const int*)p)[i];
}

// prep: zero output + segment boundaries via flat parallel scan (no dependent loads)
__global__ void __launch_bounds__(256)
prep_kernel(const void* __restrict__ idxraw, float* __restrict__ out,
            int out_n, int N)
{
    const int gtid   = blockIdx.x * blockDim.x + threadIdx.x;
    const int stride = gridDim.x * blockDim.x;

    for (int i = gtid; i < out_n; i += stride) out[i] = 0.f;

    const bool is64 = (((const int*)idxraw)[(N - 2) | 1] == 0);
    for (int i = gtid; i < N; i += stride) {
        int a = (int)ld_idx(idxraw, i, is64);
        int b = (i + 1 < N) ? (int)ld_idx(idxraw, i + 1, is64) : NSEG;
        if (i == 0)
            for (int j = 0; j <= a; j++) g_bounds[j] = 0;
        for (int j = a + 1; j <= b; j++) g_bounds[j] = i + 1;
    }
}

__global__ void __launch_bounds__(NTHREADS, SPLIT)
ect_kernel(const float* __restrict__ x, const float* __restrict__ v,
           const float* __restrict__ lin, const void* __restrict__ scaleraw,
           float* __restrict__ out)
{
    // per-warp accumulators: half2 {count, tanh-sum} per (bin, t)  (4.25 KB/warp)
    __shared__ __half2 acc[NWARPS][NBINS * PITCH];

    const int tid = threadIdx.x;
    const int w   = tid >> 5;
    const int t   = tid & 31;
    const int seg  = (int)blockIdx.x / SPLIT;
    const int part = (int)blockIdx.x - seg * SPLIT;

    // zero accumulators, 16B-vectorized (4352 words = 1088 int4)
    {
        int4* z = (int4*)&acc[0][0];
        const int n16 = (NWARPS * NBINS * PITCH) / 4;
        for (int i = tid; i < n16; i += NTHREADS)
            z[i] = make_int4(0, 0, 0, 0);
    }

    const int segS = g_bounds[seg];
    const int segE = g_bounds[seg + 1];

    // scale: int32/int64 low word, or float32
    int s_i = *(const int*)scaleraw;
    const float scale = (s_i > 0 && s_i < 1000000) ? (float)s_i
                                                   : *(const float*)scaleraw;

    const float lin0   = lin[0];
    const float dl     = (lin[SDIM - 1] - lin0) * (1.0f / (SDIM - 1));
    const float inv_dl = 1.0f / dl;
    const float K2     = -0.5f * scale * dl;      // tanh arg scale
    const float nb     = -lin0 * inv_dl;
    const float MAGIC  = 12582912.0f;             // 2^23 + 2^22
    const unsigned MAGICI = 0x4B400000u;

    const float v0 = v[t], v1 = v[TDIM + t], v2 = v[2 * TDIM + t];

    // bin -> smem byte address in ONE IMAD: off = bits(u+MAGIC)*128 + adj
    const unsigned sbase = (unsigned)__cvta_generic_to_shared(&acc[0][0]);
    const unsigned adj   = sbase + (unsigned)(w * NBINS * PITCH * 4)
                         + (unsigned)(t * 4) + 128u - MAGICI * 128u;  // mod 2^32

    const int chunk = (segE - segS + SPLIT - 1) / SPLIT;
    int start = segS + part * chunk;
    if (start > segE) start = segE;
    int end = start + chunk;
    if (end > segE) end = segE;

    int gs = (start + 3) & ~3;                    // first float4-aligned node
    if (gs > end) gs = end;
    const int ge = gs + ((end - gs) & ~3);

    // sig(s) ~ 0 (s<r), 0.5+0.5*tanh (s=r), 1 (s>r); accumulate {1, tanh}
    // at bin = r+1; 0.5/0.5 affine applied once per bin in epilogue.
    auto proc = [&](float nh) {
        float u = fmaf(nh, inv_dl, nb);
        u = fminf(fmaxf(u, -0.6f), 32.4f);
        float f = u + MAGIC;                       // rint via magic number
        float r = f - MAGIC;
        float z = K2 * (u - r);
        float th; asm("tanh.approx.f32 %0, %1;" : "=f"(th) : "f"(z));
        __half2 inc = __floats2half2_rn(1.0f, th); // one CVT: {count, tanh}
        unsigned incu = *reinterpret_cast<unsigned*>(&inc);
        unsigned off = __float_as_uint(f) * 128u + adj;   // single IMAD
        unsigned cur;
        asm volatile("ld.shared.b32 %0, [%1];" : "=r"(cur) : "r"(off));
        __half2 ch = *reinterpret_cast<__half2*>(&cur);
        __half2 ih = *reinterpret_cast<__half2*>(&incu);
        ch = __hadd2(ch, ih);
        unsigned res = *reinterpret_cast<unsigned*>(&ch);
        asm volatile("st.shared.b32 [%0], %1;" :: "r"(off), "r"(res));
    };

    // main loop: 4 nodes/iter, 3x float4 broadcast loads
    for (int n = gs + w * 4; n < ge; n += NWARPS * 4) {
        const float4* xp = (const float4*)(x + 3 * n);
        float4 A = __ldg(xp), B = __ldg(xp + 1), C = __ldg(xp + 2);
        float nh0 = fmaf(A.z, v2, fmaf(A.y, v1, A.x * v0));
        float nh1 = fmaf(B.y, v2, fmaf(B.x, v1, A.w * v0));
        float nh2 = fmaf(C.x, v2, fmaf(B.w, v1, B.z * v0));
        float nh3 = fmaf(C.w, v2, fmaf(C.z, v1, C.y * v0));
        proc(nh0); proc(nh1); proc(nh2); proc(nh3);
    }
    // scalar remainders (<= 3 each side), warp 0
    if (w == 0) {
        for (int n = start; n < gs; n++) {
            const float* xp = x + 3 * n;
            proc(fmaf(__ldg(xp + 2), v2, fmaf(__ldg(xp + 1), v1, __ldg(xp) * v0)));
        }
        for (int n = ge; n < end; n++) {
            const float* xp = x + 3 * n;
            proc(fmaf(__ldg(xp + 2), v2, fmaf(__ldg(xp + 1), v1, __ldg(xp) * v0)));
        }
    }
    __syncthreads();

    // warp 0: reduce 4 copies + prefix over bins + RED into out
    // out[s] = prefixIncl(C)[s] + 0.5*(C[s+1] + Th[s+1])
    if (w == 0) {
        float run = 0.f;
        float* ob = out + seg * (SDIM * TDIM) + t;
        #pragma unroll
        for (int b = 0; b <= SDIM; b++) {
            int o = b * PITCH + t;
            __half2 h0 = acc[0][o], h1 = acc[1][o], h2 = acc[2][o], h3 = acc[3][o];
            float2 f0 = __half22float2(h0), f1 = __half22float2(h1);
            float2 f2 = __half22float2(h2), f3 = __half22float2(h3);
            float C  = (f0.x + f1.x) + (f2.x + f3.x);
            float Th = (f0.y + f1.y) + (f2.y + f3.y);
            if (b >= 1) atomicAdd(ob + (b - 1) * TDIM, fmaf(0.5f, C + Th, run));
            run += C;
        }
    }
}

extern "C" void kernel_launch(void* const* d_in, const int* in_sizes, int n_in,
                              void* d_out, int out_size)
{
    const float* x     = (const float*)d_in[0];
    const void*  index = d_in[1];
    const float* v     = (const float*)d_in[2];
    const float* lin   = (const float*)d_in[3];
    const void*  scale = d_in[4];
    float*       out   = (float*)d_out;
    const int N = in_sizes[1];

    prep_kernel<<<256, 256>>>(index, out, out_size, N);
    ect_kernel<<<NSEG * SPLIT, NTHREADS>>>(x, v, lin, scale, out);
}

// round 8
// speedup vs baseline: 1.1530x; 1.1530x over previous
#include <cuda_runtime.h>
#include <cuda_fp16.h>

#define NSEG   128
#define SDIM   32
#define TDIM   32
#define NWARPS 4
#define NTHREADS 128
#define SPLIT  12
#define NBINS  34                 // bin = r+1, r in [-1, 32]
#define PITCH  32                 // word addr = 32*bin + t  ->  bank = t (conflict-free)

__device__ int g_bounds[NSEG + 1];

__device__ __forceinline__ long long ld_idx(const void* p, int i, bool is64) {
    return is64 ? ((const long long*)p)[i] : (long long)((const int*)p)[i];
}

// prep: zero output (float4) + segment boundaries via vectorized flat scan
__global__ void __launch_bounds__(256)
prep_kernel(const void* __restrict__ idxraw, float* __restrict__ out,
            int out_n, int N)
{
    const int gtid   = blockIdx.x * blockDim.x + threadIdx.x;
    const int stride = gridDim.x * blockDim.x;

    // zero out, vectorized (out_n = 131072, multiple of 4)
    float4* o4 = (float4*)out;
    for (int i = gtid; i < (out_n >> 2); i += stride)
        o4[i] = make_float4(0.f, 0.f, 0.f, 0.f);

    const bool is64 = (((const int*)idxraw)[(N - 2) | 1] == 0);

    // each thread scans 8 consecutive entries + the next one
    const int base = gtid * 8;
    if (base >= N) return;
    int vals[9];
    if (is64) {
        const longlong2* p = (const longlong2*)idxraw;
        #pragma unroll
        for (int k = 0; k < 4; k++) {
            int ii = (base >> 1) + k;
            if (base + 2 * k < N) {
                longlong2 v2 = __ldg(p + ii);
                vals[2 * k]     = (int)v2.x;
                vals[2 * k + 1] = (int)v2.y;
            }
        }
    } else {
        const int4* p = (const int4*)idxraw;
        #pragma unroll
        for (int k = 0; k < 2; k++) {
            if (base + 4 * k < N) {
                int4 v4 = __ldg(p + (base >> 2) + k);
                vals[4 * k] = v4.x; vals[4 * k + 1] = v4.y;
                vals[4 * k + 2] = v4.z; vals[4 * k + 3] = v4.w;
            }
        }
    }
    vals[8] = (base + 8 < N) ? (int)ld_idx(idxraw, base + 8, is64) : NSEG;

    if (base == 0)
        for (int j = 0; j <= vals[0]; j++) g_bounds[j] = 0;
    #pragma unroll
    for (int k = 0; k < 8; k++) {
        int i = base + k;
        if (i + 1 <= N - 1 || i == N - 1) {
            int a = vals[k];
            int b = (i == N - 1) ? NSEG : vals[k + 1];
            for (int j = a + 1; j <= b; j++) g_bounds[j] = i + 1;
        }
    }
}

__global__ void __launch_bounds__(NTHREADS, SPLIT)
ect_kernel(const float* __restrict__ x, const float* __restrict__ v,
           const float* __restrict__ lin, const void* __restrict__ scaleraw,
           float* __restrict__ out)
{
    // per-warp accumulators: half2 {count, tanh-sum} per (bin, t)  (4.25 KB/warp)
    __shared__ __half2 acc[NWARPS][NBINS * PITCH];

    const int tid = threadIdx.x;
    const int w   = tid >> 5;
    const int t   = tid & 31;
    const int seg  = (int)blockIdx.x / SPLIT;
    const int part = (int)blockIdx.x - seg * SPLIT;

    // zero accumulators, 16B-vectorized
    {
        int4* z = (int4*)&acc[0][0];
        const int n16 = (NWARPS * NBINS * PITCH) / 4;
        for (int i = tid; i < n16; i += NTHREADS)
            z[i] = make_int4(0, 0, 0, 0);
    }

    const int segS = g_bounds[seg];
    const int segE = g_bounds[seg + 1];

    // scale: int32/int64 low word, or float32
    int s_i = *(const int*)scaleraw;
    const float scale = (s_i > 0 && s_i < 1000000) ? (float)s_i
                                                   : *(const float*)scaleraw;

    const float lin0   = lin[0];
    const float dl     = (lin[SDIM - 1] - lin0) * (1.0f / (SDIM - 1));
    const float inv_dl = 1.0f / dl;
    const float K2     = -0.5f * scale * dl;      // tanh arg scale
    const float nb     = -lin0 * inv_dl;
    const float MAGIC  = 12582912.0f;             // 2^23 + 2^22
    const unsigned MAGICI = 0x4B400000u;
    const float K2M    = K2 * MAGIC;              // for z = fma(u,K2, fma(f,-K2,K2M))

    const float v0 = v[t], v1 = v[TDIM + t], v2 = v[2 * TDIM + t];

    // bin -> smem byte address in ONE IMAD: off = bits(u+MAGIC)*128 + adj
    const unsigned sbase = (unsigned)__cvta_generic_to_shared(&acc[0][0]);
    const unsigned adj   = sbase + (unsigned)(w * NBINS * PITCH * 4)
                         + (unsigned)(t * 4) + 128u - MAGICI * 128u;  // mod 2^32

    const int chunk = (segE - segS + SPLIT - 1) / SPLIT;
    int start = segS + part * chunk;
    if (start > segE) start = segE;
    int end = start + chunk;
    if (end > segE) end = segE;

    int gs = (start + 3) & ~3;                    // first float4-aligned node
    if (gs > end) gs = end;
    const int ge = gs + ((end - gs) & ~3);

    // sig(s) ~ 0 (s<r), 0.5+0.5*tanh (s=r), 1 (s>r); accumulate {1, tanh}
    // at bin = r+1; 0.5/0.5 affine applied once per bin in epilogue.
    auto proc = [&](float nh) {
        float u = fmaf(nh, inv_dl, nb);
        u = fminf(fmaxf(u, -0.6f), 32.4f);
        float f = u + MAGIC;                       // rint via magic number
        float t1 = fmaf(f, -K2, K2M);              // = -K2*rint(u)
        float z  = fmaf(u, K2, t1);                // = K2*(u - rint(u))
        float th; asm("tanh.approx.f32 %0, %1;" : "=f"(th) : "f"(z));
        __half2 inc = __floats2half2_rn(1.0f, th); // one cvt: {count, tanh}
        unsigned incu = *reinterpret_cast<unsigned*>(&inc);
        unsigned off = __float_as_uint(f) * 128u + adj;   // single IMAD
        unsigned cur;
        asm volatile("ld.shared.b32 %0, [%1];" : "=r"(cur) : "r"(off));
        __half2 ch = *reinterpret_cast<__half2*>(&cur);
        __half2 ih = *reinterpret_cast<__half2*>(&incu);
        ch = __hadd2(ch, ih);
        unsigned res = *reinterpret_cast<unsigned*>(&ch);
        asm volatile("st.shared.b32 [%0], %1;" :: "r"(off), "r"(res));
    };

    // main loop: 4 nodes/iter, 3x float4 broadcast loads
    for (int n = gs + w * 4; n < ge; n += NWARPS * 4) {
        const float4* xp = (const float4*)(x + 3 * n);
        float4 A = __ldg(xp), B = __ldg(xp + 1), C = __ldg(xp + 2);
        float nh0 = fmaf(A.z, v2, fmaf(A.y, v1, A.x * v0));
        float nh1 = fmaf(B.y, v2, fmaf(B.x, v1, A.w * v0));
        float nh2 = fmaf(C.x, v2, fmaf(B.w, v1, B.z * v0));
        float nh3 = fmaf(C.w, v2, fmaf(C.z, v1, C.y * v0));
        proc(nh0); proc(nh1); proc(nh2); proc(nh3);
    }
    // scalar remainders (<= 3 each side), warp 0
    if (w == 0) {
        for (int n = start; n < gs; n++) {
            const float* xp = x + 3 * n;
            proc(fmaf(__ldg(xp + 2), v2, fmaf(__ldg(xp + 1), v1, __ldg(xp) * v0)));
        }
        for (int n = ge; n < end; n++) {
            const float* xp = x + 3 * n;
            proc(fmaf(__ldg(xp + 2), v2, fmaf(__ldg(xp + 1), v1, __ldg(xp) * v0)));
        }
    }
    __syncthreads();

    // warp 0: reduce 4 copies + prefix over bins + RED into out
    // out[s] = prefixIncl(C)[s] + 0.5*(C[s+1] + Th[s+1])
    if (w == 0) {
        float run = 0.f;
        float* ob = out + seg * (SDIM * TDIM) + t;
        #pragma unroll
        for (int b = 0; b <= SDIM; b++) {
            int o = b * PITCH + t;
            __half2 h0 = acc[0][o], h1 = acc[1][o], h2 = acc[2][o], h3 = acc[3][o];
            float2 f0 = __half22float2(h0), f1 = __half22float2(h1);
            float2 f2 = __half22float2(h2), f3 = __half22float2(h3);
            float C  = (f0.x + f1.x) + (f2.x + f3.x);
            float Th = (f0.y + f1.y) + (f2.y + f3.y);
            if (b >= 1) atomicAdd(ob + (b - 1) * TDIM, fmaf(0.5f, C + Th, run));
            run += C;
        }
    }
}

extern "C" void kernel_launch(void* const* d_in, const int* in_sizes, int n_in,
                              void* d_out, int out_size)
{
    const float* x     = (const float*)d_in[0];
    const void*  index = d_in[1];
    const float* v     = (const float*)d_in[2];
    const float* lin   = (const float*)d_in[3];
    const void*  scale = d_in[4];
    float*       out   = (float*)d_out;
    const int N = in_sizes[1];

    const int scan_threads = (N + 7) / 8;
    const int prep_blocks  = (scan_threads + 255) / 256 > 128
                           ? (scan_threads + 255) / 256 : 128;
    prep_kernel<<<prep_blocks, 256>>>(index, out, out_size, N);
    ect_kernel<<<NSEG * SPLIT, NTHREADS>>>(x, v, lin, scale, out);
}